// round 16
// baseline (speedup 1.0000x reference)
#include <cuda_runtime.h>
#include <cstdint>

#define BATCH    16384
#define NFIELDS  50
#define DIM      64
#define L1DIM    128
#define L2DIM    64
#define ROWS     4       // batch rows per block
#define THREADS  64      // 2 warps: gather 2 rows/warp; MLP col-split (4 rows each)

// dynamic shared layout (floats):
//   sFM : ROWS*64   (reused as sH2 after h1)
//   sH1 : ROWS*128
#define SMEM_FLOATS (ROWS*64 + ROWS*128)

__global__ __launch_bounds__(THREADS, 16)
void nfm_fused_kernel(const int*   __restrict__ features,
                      const float* __restrict__ emb,
                      const float* __restrict__ bias_table,
                      const float* __restrict__ w_bias,
                      const float* __restrict__ W1,
                      const float* __restrict__ b1,
                      const float* __restrict__ W2,
                      const float* __restrict__ b2,
                      const float* __restrict__ Wp,
                      const float* __restrict__ bp,
                      float*       __restrict__ out)
{
    extern __shared__ float sm[];
    float* sFM = sm;               // ROWS*64
    float* sH1 = sm + ROWS * 64;   // ROWS*128
    float* sH2 = sFM;              // overlay (FM dead after h1)

    const int tid  = threadIdx.x;
    const int lane = tid & 31;
    const int wid  = tid >> 5;     // 0..1
    const int row0 = blockIdx.x * ROWS;
    const int half = lane >> 4;    // 0 -> row A, 1 -> row B
    const int l16  = lane & 15;

    // ---- gather + FM bi-interaction: warp w owns rows 2w, 2w+1 as ONE pair --
    // lanes 0-15 = row A, 16-31 = row B, 4 dims/lane (float4): one LDG.128 per
    // field serves both rows. Indices uniform (int2), bias uniform loads.
    float bsA = 0.f, bsB = 0.f;                  // uniform row biases (registers)
    {
        const int rA = wid * 2;
        const int rB = rA + 1;
        const int2* frA = reinterpret_cast<const int2*>(
                              features + (long)(row0 + rA) * NFIELDS);
        const int2* frB = reinterpret_cast<const int2*>(
                              features + (long)(row0 + rB) * NFIELDS);

        float4 s  = make_float4(0.f, 0.f, 0.f, 0.f);
        float4 sq = make_float4(0.f, 0.f, 0.f, 0.f);

        #pragma unroll
        for (int f2 = 0; f2 < NFIELDS / 2; ++f2) {        // 25 int2 per row
            const int2 ia2 = __ldg(frA + f2);             // uniform
            const int2 ib2 = __ldg(frB + f2);             // uniform
            {
                const int idx = half ? ib2.x : ia2.x;
                const float4 v = *reinterpret_cast<const float4*>(
                                     emb + (long)idx * DIM + l16 * 4);
                bsA += __ldg(bias_table + ia2.x);
                bsB += __ldg(bias_table + ib2.x);
                s.x  += v.x;       s.y  += v.y;       s.z  += v.z;       s.w  += v.w;
                sq.x += v.x * v.x; sq.y += v.y * v.y; sq.z += v.z * v.z; sq.w += v.w * v.w;
            }
            {
                const int idx = half ? ib2.y : ia2.y;
                const float4 v = *reinterpret_cast<const float4*>(
                                     emb + (long)idx * DIM + l16 * 4);
                bsA += __ldg(bias_table + ia2.y);
                bsB += __ldg(bias_table + ib2.y);
                s.x  += v.x;       s.y  += v.y;       s.z  += v.z;       s.w  += v.w;
                sq.x += v.x * v.x; sq.y += v.y * v.y; sq.z += v.z * v.z; sq.w += v.w * v.w;
            }
        }
        float4 fm;
        fm.x = 0.5f * (s.x * s.x - sq.x);
        fm.y = 0.5f * (s.y * s.y - sq.y);
        fm.z = 0.5f * (s.z * s.z - sq.z);
        fm.w = 0.5f * (s.w * s.w - sq.w);
        const int rl = half ? rB : rA;
        *reinterpret_cast<float4*>(sFM + rl * DIM + l16 * 4) = fm;
    }
    __syncthreads();

    // ---- h1 = relu(FM @ W1 + b1): warp w owns column half [64w, 64w+64) -----
    // All 4 rows per warp; float2 weights; per-block W1 bytes = 32 KB / 4 rows
    // = 8 KB/row (same amortization as the best kernel).
    {
        const int c2 = wid * 64 + lane * 2;     // thread owns cols c2, c2+1
        const float2 bias1 = __ldg(reinterpret_cast<const float2*>(b1 + c2));
        float acc[4][2];
        #pragma unroll
        for (int i = 0; i < 4; ++i) { acc[i][0] = bias1.x; acc[i][1] = bias1.y; }

        #pragma unroll
        for (int d = 0; d < DIM; ++d) {
            const float2 w = __ldg(reinterpret_cast<const float2*>(
                                       W1 + d * L1DIM + c2));
            #pragma unroll
            for (int i = 0; i < 4; ++i) {
                const float fv = sFM[i * DIM + d];   // broadcast
                acc[i][0] += fv * w.x;
                acc[i][1] += fv * w.y;
            }
        }
        #pragma unroll
        for (int i = 0; i < 4; ++i) {
            float2 r;
            r.x = fmaxf(acc[i][0], 0.f);
            r.y = fmaxf(acc[i][1], 0.f);
            *reinterpret_cast<float2*>(sH1 + i * L1DIM + c2) = r;
        }
    }
    __syncthreads();   // sFM dead; safe to overlay sH2

    // ---- h2 = relu(H1 @ W2 + b2): warp w owns cols [32w, 32w+32) ------------
    {
        const int c = wid * 32 + lane;          // thread owns col c
        const float bias2 = __ldg(b2 + c);
        float acc[4] = { bias2, bias2, bias2, bias2 };

        #pragma unroll
        for (int d = 0; d < L1DIM; ++d) {
            const float w = __ldg(W2 + d * L2DIM + c);
            #pragma unroll
            for (int i = 0; i < 4; ++i)
                acc[i] += sH1[i * L1DIM + d] * w;   // broadcast
        }
        #pragma unroll
        for (int i = 0; i < 4; ++i)
            sH2[i * L2DIM + c] = fmaxf(acc[i], 0.f);
    }
    __syncthreads();

    // ---- pred = H2 @ Wp + bp: warp w -> its gathered rows 2w, 2w+1 ----------
    {
        const float gb  = __ldg(w_bias);
        const float bpv = __ldg(bp);
        const float wp0 = __ldg(Wp + lane);
        const float wp1 = __ldg(Wp + lane + 32);
        const float rowBias[2] = { bsA, bsB };
        #pragma unroll
        for (int i = 0; i < 2; ++i) {
            const int rl = wid * 2 + i;
            float v = sH2[rl * L2DIM + lane]      * wp0
                    + sH2[rl * L2DIM + lane + 32] * wp1;
            #pragma unroll
            for (int o = 16; o; o >>= 1) v += __shfl_down_sync(0xffffffffu, v, o);
            if (lane == 0) out[row0 + rl] = v + bpv + rowBias[i] + gb;
        }
    }
}

extern "C" void kernel_launch(void* const* d_in, const int* in_sizes, int n_in,
                              void* d_out, int out_size)
{
    const int*   features   = (const int*)  d_in[0];
    // d_in[1] = labels (unused, shape-only in reference)
    const float* emb        = (const float*)d_in[2];
    const float* bias_table = (const float*)d_in[3];
    const float* w_bias     = (const float*)d_in[4];
    const float* W1         = (const float*)d_in[5];
    const float* b1         = (const float*)d_in[6];
    const float* W2         = (const float*)d_in[7];
    const float* b2         = (const float*)d_in[8];
    const float* Wp         = (const float*)d_in[9];
    const float* bp         = (const float*)d_in[10];
    float*       out        = (float*)d_out;

    const int smem_bytes = SMEM_FLOATS * sizeof(float);   // 3 KB
    cudaFuncSetAttribute(nfm_fused_kernel,
                         cudaFuncAttributeMaxDynamicSharedMemorySize, smem_bytes);

    nfm_fused_kernel<<<BATCH / ROWS, THREADS, smem_bytes>>>(
        features, emb, bias_table, w_bias, W1, b1, W2, b2, Wp, bp, out);
}

// round 17
// speedup vs baseline: 1.0691x; 1.0691x over previous
#include <cuda_runtime.h>
#include <cstdint>

#define BATCH    16384
#define NFIELDS  50
#define DIM      64
#define L1DIM    128
#define L2DIM    64
#define ROWS     8       // batch rows per block
#define THREADS  64      // 2 warps: gather 4 rows/warp; MLP col-split, 8 rows deep

// dynamic shared layout (floats):
//   sFM : ROWS*64   (reused as sH2 after h1)
//   sH1 : ROWS*128
#define SMEM_FLOATS (ROWS*64 + ROWS*128)

__global__ __launch_bounds__(THREADS, 16)
void nfm_fused_kernel(const int*   __restrict__ features,
                      const float* __restrict__ emb,
                      const float* __restrict__ bias_table,
                      const float* __restrict__ w_bias,
                      const float* __restrict__ W1,
                      const float* __restrict__ b1,
                      const float* __restrict__ W2,
                      const float* __restrict__ b2,
                      const float* __restrict__ Wp,
                      const float* __restrict__ bp,
                      float*       __restrict__ out)
{
    extern __shared__ float sm[];
    float* sFM = sm;               // ROWS*64
    float* sH1 = sm + ROWS * 64;   // ROWS*128
    float* sH2 = sFM;              // overlay (FM dead after h1)

    const int tid  = threadIdx.x;
    const int lane = tid & 31;
    const int wid  = tid >> 5;     // 0..1
    const int row0 = blockIdx.x * ROWS;
    const int half = lane >> 4;    // 0 -> row A, 1 -> row B of a pair
    const int l16  = lane & 15;

    // ---- gather + FM bi-interaction: warp w owns rows 4w..4w+3 (2 pairs) ----
    // Identical to the 43.7us kernel: lanes 0-15 = row A, 16-31 = row B,
    // 4 dims/lane (float4) -> one LDG.128 per field serves both rows.
    // Indices uniform (int2), bias via uniform loads, kept in registers.
    float rowBias[4];
    #pragma unroll
    for (int p = 0; p < 2; ++p) {
        const int rA = wid * 4 + p * 2;
        const int rB = rA + 1;
        const int2* frA = reinterpret_cast<const int2*>(
                              features + (long)(row0 + rA) * NFIELDS);
        const int2* frB = reinterpret_cast<const int2*>(
                              features + (long)(row0 + rB) * NFIELDS);

        float4 s  = make_float4(0.f, 0.f, 0.f, 0.f);
        float4 sq = make_float4(0.f, 0.f, 0.f, 0.f);
        float  bsA = 0.f, bsB = 0.f;

        #pragma unroll
        for (int f2 = 0; f2 < NFIELDS / 2; ++f2) {        // 25 int2 per row
            const int2 ia2 = __ldg(frA + f2);             // uniform
            const int2 ib2 = __ldg(frB + f2);             // uniform
            {
                const int idx = half ? ib2.x : ia2.x;
                const float4 v = *reinterpret_cast<const float4*>(
                                     emb + (long)idx * DIM + l16 * 4);
                bsA += __ldg(bias_table + ia2.x);
                bsB += __ldg(bias_table + ib2.x);
                s.x  += v.x;       s.y  += v.y;       s.z  += v.z;       s.w  += v.w;
                sq.x += v.x * v.x; sq.y += v.y * v.y; sq.z += v.z * v.z; sq.w += v.w * v.w;
            }
            {
                const int idx = half ? ib2.y : ia2.y;
                const float4 v = *reinterpret_cast<const float4*>(
                                     emb + (long)idx * DIM + l16 * 4);
                bsA += __ldg(bias_table + ia2.y);
                bsB += __ldg(bias_table + ib2.y);
                s.x  += v.x;       s.y  += v.y;       s.z  += v.z;       s.w  += v.w;
                sq.x += v.x * v.x; sq.y += v.y * v.y; sq.z += v.z * v.z; sq.w += v.w * v.w;
            }
        }
        float4 fm;
        fm.x = 0.5f * (s.x * s.x - sq.x);
        fm.y = 0.5f * (s.y * s.y - sq.y);
        fm.z = 0.5f * (s.z * s.z - sq.z);
        fm.w = 0.5f * (s.w * s.w - sq.w);
        const int rl = half ? rB : rA;
        *reinterpret_cast<float4*>(sFM + rl * DIM + l16 * 4) = fm;
        rowBias[p * 2]     = bsA;      // uniform values
        rowBias[p * 2 + 1] = bsB;
    }
    __syncthreads();

    // ---- h1 = relu(FM @ W1 + b1): col-split, ALL 8 rows per warp ------------
    // warp w owns cols [64w, 64w+64); W1 bytes/block = 32 KB for 8 rows
    // = 2 KB/row (HALF the previous per-row weight traffic).
    {
        const int c2 = wid * 64 + lane * 2;     // thread owns cols c2, c2+1
        const float2 bias1 = __ldg(reinterpret_cast<const float2*>(b1 + c2));
        float acc[8][2];
        #pragma unroll
        for (int i = 0; i < 8; ++i) { acc[i][0] = bias1.x; acc[i][1] = bias1.y; }

        #pragma unroll
        for (int d = 0; d < DIM; ++d) {
            const float2 w = __ldg(reinterpret_cast<const float2*>(
                                       W1 + d * L1DIM + c2));
            #pragma unroll
            for (int i = 0; i < 8; ++i) {
                const float fv = sFM[i * DIM + d];   // broadcast
                acc[i][0] += fv * w.x;
                acc[i][1] += fv * w.y;
            }
        }
        #pragma unroll
        for (int i = 0; i < 8; ++i) {
            float2 r;
            r.x = fmaxf(acc[i][0], 0.f);
            r.y = fmaxf(acc[i][1], 0.f);
            *reinterpret_cast<float2*>(sH1 + i * L1DIM + c2) = r;
        }
    }
    __syncthreads();   // sFM dead; safe to overlay sH2

    // ---- h2 = relu(H1 @ W2 + b2): col-split, ALL 8 rows per warp ------------
    // warp w owns cols [32w, 32w+32); W2 bytes/block = 32 KB / 8 rows = 2 KB/row.
    {
        const int c = wid * 32 + lane;          // thread owns col c
        const float bias2 = __ldg(b2 + c);
        float acc[8];
        #pragma unroll
        for (int i = 0; i < 8; ++i) acc[i] = bias2;

        #pragma unroll
        for (int d = 0; d < L1DIM; ++d) {
            const float w = __ldg(W2 + d * L2DIM + c);
            #pragma unroll
            for (int i = 0; i < 8; ++i)
                acc[i] += sH1[i * L1DIM + d] * w;   // broadcast
        }
        #pragma unroll
        for (int i = 0; i < 8; ++i)
            sH2[i * L2DIM + c] = fmaxf(acc[i], 0.f);
    }
    __syncthreads();

    // ---- pred = H2 @ Wp + bp: warp w -> its gathered rows 4w..4w+3 ----------
    {
        const float gb  = __ldg(w_bias);
        const float bpv = __ldg(bp);
        const float wp0 = __ldg(Wp + lane);
        const float wp1 = __ldg(Wp + lane + 32);
        #pragma unroll
        for (int i = 0; i < 4; ++i) {
            const int rl = wid * 4 + i;
            float v = sH2[rl * L2DIM + lane]      * wp0
                    + sH2[rl * L2DIM + lane + 32] * wp1;
            #pragma unroll
            for (int o = 16; o; o >>= 1) v += __shfl_down_sync(0xffffffffu, v, o);
            if (lane == 0) out[row0 + rl] = v + bpv + rowBias[i] + gb;
        }
    }
}

extern "C" void kernel_launch(void* const* d_in, const int* in_sizes, int n_in,
                              void* d_out, int out_size)
{
    const int*   features   = (const int*)  d_in[0];
    // d_in[1] = labels (unused, shape-only in reference)
    const float* emb        = (const float*)d_in[2];
    const float* bias_table = (const float*)d_in[3];
    const float* w_bias     = (const float*)d_in[4];
    const float* W1         = (const float*)d_in[5];
    const float* b1         = (const float*)d_in[6];
    const float* W2         = (const float*)d_in[7];
    const float* b2         = (const float*)d_in[8];
    const float* Wp         = (const float*)d_in[9];
    const float* bp         = (const float*)d_in[10];
    float*       out        = (float*)d_out;

    const int smem_bytes = SMEM_FLOATS * sizeof(float);   // 6 KB
    cudaFuncSetAttribute(nfm_fused_kernel,
                         cudaFuncAttributeMaxDynamicSharedMemorySize, smem_bytes);

    nfm_fused_kernel<<<BATCH / ROWS, THREADS, smem_bytes>>>(
        features, emb, bias_table, w_bias, W1, b1, W2, b2, Wp, bp, out);
}